// round 14
// baseline (speedup 1.0000x reference)
#include <cuda_runtime.h>

#define B_ 4
#define C_ 64
#define H_ 64
#define W_ 192
#define D_ 24
#define HW_ (H_*W_)

// Z = src·M (stored tf32-rounded); dot maps du = src·u, dv = src·v.
__device__ float g_Z[2][B_][HW_][C_];
__device__ float g_du[2][B_][HW_];
__device__ float g_dv[2][B_][HW_];
__device__ float g_Mt[C_][C_];   // g_Mt[j][i] = sum_c kw[c][j]*qw[c][i]
__device__ float g_uv[2][C_];
__device__ float g_s0;

__device__ __forceinline__ unsigned to_tf32(float f) {
    unsigned u;
    asm("cvt.rna.tf32.f32 %0, %1;" : "=r"(u) : "f"(f));
    return u;
}
__device__ __forceinline__ void mma_tf32(float& c0, float& c1, float& c2, float& c3,
                                         unsigned a0, unsigned a1, unsigned a2, unsigned a3,
                                         unsigned b0, unsigned b1) {
    asm volatile(
        "mma.sync.aligned.m16n8k8.row.col.f32.tf32.tf32.f32 "
        "{%0,%1,%2,%3}, {%4,%5,%6,%7}, {%8,%9}, {%0,%1,%2,%3};"
        : "+f"(c0), "+f"(c1), "+f"(c2), "+f"(c3)
        : "r"(a0), "r"(a1), "r"(a2), "r"(a3), "r"(b0), "r"(b1));
}

// ---------------------------------------------------------------------------
// Prep: blocks 0..63 -> one M row each (4-way lane split + shfl);
// block 64 -> u, v, s0.
// ---------------------------------------------------------------------------
__global__ void prep_kernel(const float* __restrict__ qw, const float* __restrict__ qb,
                            const float* __restrict__ kw, const float* __restrict__ kb)
{
    const int tid = threadIdx.x, bid = blockIdx.x;
    if (bid < 64) {
        const int j = bid, i = tid >> 2, q = tid & 3;
        float acc = 0.f;
        #pragma unroll
        for (int c = 0; c < 16; ++c)
            acc += __ldg(&kw[(q * 16 + c) * 64 + j]) * __ldg(&qw[(q * 16 + c) * 64 + i]);
        acc += __shfl_xor_sync(0xffffffffu, acc, 1);
        acc += __shfl_xor_sync(0xffffffffu, acc, 2);
        if (q == 0) g_Mt[j][i] = acc;
    } else {
        if (tid < 256) {
            const int m = tid >> 7, i = (tid >> 1) & 63, q = tid & 1;
            const float* wm = m ? kw : qw;
            const float* bm = m ? qb : kb;
            float acc = 0.f;
            #pragma unroll
            for (int c = 0; c < 32; ++c)
                acc += __ldg(&wm[(q * 32 + c) * 64 + i]) * __ldg(&bm[q * 32 + c]);
            acc += __shfl_xor_sync(0xffffffffu, acc, 1);
            if (q == 0) g_uv[m][i] = acc;
        }
        if (tid >= 224) {
            const int lane = tid & 31;
            float s = __ldg(&qb[lane]) * __ldg(&kb[lane])
                    + __ldg(&qb[lane + 32]) * __ldg(&kb[lane + 32]);
            s += __shfl_xor_sync(0xffffffffu, s, 1);
            s += __shfl_xor_sync(0xffffffffu, s, 2);
            s += __shfl_xor_sync(0xffffffffu, s, 4);
            s += __shfl_xor_sync(0xffffffffu, s, 8);
            s += __shfl_xor_sync(0xffffffffu, s, 16);
            if (lane == 0) g_s0 = s;
        }
    }
}

// ---------------------------------------------------------------------------
// Z kernel: Z = src·M, single tf32 mma per k-step (both operands tf32).
// Full 192-pixel row blocks (grid 512 -> single wave at 4 CTAs/SM).
// smem = in_s only (51200 B). M / uv via L1-hot __ldg.
// ---------------------------------------------------------------------------
__global__ __launch_bounds__(256, 4) void z_kernel(
    const float* __restrict__ x, const float* __restrict__ y)
{
    extern __shared__ float zsm[];
    float* in_s = zsm;              // 64*200 = 12800 floats
    const int h = blockIdx.x, b = blockIdx.y, srcIdx = blockIdx.z;
    const float* src = srcIdx ? y : x;
    const int tid = threadIdx.x;

    #pragma unroll
    for (int e4 = tid; e4 < 3072; e4 += 256) {
        int k = e4 / 48, w4 = e4 - k * 48;
        *(float4*)&in_s[k * 200 + w4 * 4] =
            *(const float4*)(src + ((size_t)(b * 64 + k)) * HW_ + h * 192 + w4 * 4);
    }
    __syncthreads();

    const int warp = tid >> 5, lane = tid & 31;
    const int g = lane >> 2, tig = lane & 3;
    const int n0 = warp * 8;

    unsigned bh[8][2];
    #pragma unroll
    for (int ks = 0; ks < 8; ks++) {
        bh[ks][0] = to_tf32(__ldg(&g_Mt[n0 + g][ks * 8 + tig]));
        bh[ks][1] = to_tf32(__ldg(&g_Mt[n0 + g][ks * 8 + tig + 4]));
    }

    float* outp = &g_Z[srcIdx][b][h * W_][0];
    #pragma unroll 1
    for (int mt = 0; mt < 12; ++mt) {
        const int m0 = mt * 16;
        float c0 = 0.f, c1 = 0.f, c2 = 0.f, c3 = 0.f;
        #pragma unroll
        for (int ks = 0; ks < 8; ks++) {
            unsigned ah0 = to_tf32(in_s[(ks * 8 + tig) * 200 + m0 + g]);
            unsigned ah1 = to_tf32(in_s[(ks * 8 + tig) * 200 + m0 + g + 8]);
            unsigned ah2 = to_tf32(in_s[(ks * 8 + tig + 4) * 200 + m0 + g]);
            unsigned ah3 = to_tf32(in_s[(ks * 8 + tig + 4) * 200 + m0 + g + 8]);
            mma_tf32(c0, c1, c2, c3, ah0, ah1, ah2, ah3, bh[ks][0], bh[ks][1]);
        }
        *(uint2*)(outp + (size_t)(m0 + g) * 64 + n0 + 2 * tig) =
            make_uint2(to_tf32(c0), to_tf32(c1));
        *(uint2*)(outp + (size_t)(m0 + g + 8) * 64 + n0 + 2 * tig) =
            make_uint2(to_tf32(c2), to_tf32(c3));
    }

    // dot maps (fp32 exact); u/v via uniform L1 loads
    if (tid < 192) {
        float du = 0.f, dv = 0.f;
        #pragma unroll 8
        for (int c = 0; c < 64; ++c) {
            float xv = in_s[c * 200 + tid];
            du += xv * __ldg(&g_uv[0][c]);
            dv += xv * __ldg(&g_uv[1][c]);
        }
        g_du[srcIdx][b][h * W_ + tid] = du;
        g_dv[srcIdx][b][h * W_ + tid] = dv;
    }
}

// ---------------------------------------------------------------------------
// Cost volume (gather mapping = R11 verified): S = Z·Yb^T (pure tf32 mma);
// rank-1 + dv + const folded into the gather epilogue.
// 256 thr, 69120 B, 3 CTAs/SM.
// ---------------------------------------------------------------------------
__global__ __launch_bounds__(256, 3) void cost_kernel(
    const float* __restrict__ x, const float* __restrict__ y,
    const float* __restrict__ d1, const float* __restrict__ d2,
    float* __restrict__ out)
{
    extern __shared__ float sm[];
    float* kb_s   = sm;            // 64*200 = 12800
    float* S_s    = sm + 12800;    // 16*200 = 3200
    float* q_s    = sm + 16000;    // 16*68  = 1088
    float* dvyb_s = sm + 17088;    // 192
    const int h = blockIdx.x, b = blockIdx.y, vol = blockIdx.z;
    const int tid = threadIdx.x;

    float ys  = h * (64.0f / 63.0f) - 0.5f;
    float y0f = floorf(ys);
    float ty  = ys - y0f;
    int iy0 = (int)y0f, iy1 = iy0 + 1;
    float wy0 = (iy0 >= 0 && iy0 < H_) ? (1.0f - ty) : 0.0f;
    float wy1 = (iy1 >= 0 && iy1 < H_) ? ty : 0.0f;
    int y0c = min(max(iy0, 0), H_ - 1);
    int y1c = min(max(iy1, 0), H_ - 1);
    const float wsum = wy0 + wy1;

    const float* srcB = (vol == 0) ? y : x;
    const int s2 = vol ^ 1;

    #pragma unroll
    for (int e4 = tid; e4 < 3072; e4 += 256) {
        int c = e4 / 48, w4 = e4 - c * 48;
        const float* r0 = srcB + ((size_t)(b * 64 + c) * H_ + y0c) * W_ + w4 * 4;
        const float* r1 = srcB + ((size_t)(b * 64 + c) * H_ + y1c) * W_ + w4 * 4;
        float4 a = *(const float4*)r0, cc = *(const float4*)r1;
        *(uint4*)&kb_s[c * 200 + w4 * 4] =
            make_uint4(to_tf32(wy0 * a.x + wy1 * cc.x),
                       to_tf32(wy0 * a.y + wy1 * cc.y),
                       to_tf32(wy0 * a.z + wy1 * cc.z),
                       to_tf32(wy0 * a.w + wy1 * cc.w));
    }
    if (tid < 192)
        dvyb_s[tid] = wy0 * g_dv[s2][b][y0c * W_ + tid]
                    + wy1 * g_dv[s2][b][y1c * W_ + tid];
    const float rho0 = wsum * g_s0;

    const int warp = tid >> 5, lane = tid & 31;
    const int g = lane >> 2, tig = lane & 3;
    const int sm_ = tid >> 4, sc4 = tid & 15;
    const int gd0 = tid >> 4, gw0 = tid & 15;
    const int gd1 = (tid + 256) >> 4, gw1 = tid & 15;
    const float* dispb = ((vol == 0) ? d1 : d2) + (size_t)b * D_ * HW_ + h * W_;
    const float* qbase = &g_Z[vol][b][h * W_][0];
    const float* dubase = &g_du[vol][b][h * W_];
    float* outb = out + ((size_t)(vol * B_ + b) * D_) * HW_ + h * W_;

    float4 qv = *(const float4*)(qbase + sm_ * 64 + sc4 * 4);
    *(float4*)&q_s[sm_ * 68 + sc4 * 4] = qv;
    qv = *(const float4*)(qbase + (16 + sm_) * 64 + sc4 * 4);
    float dsp0 = __ldg(&dispb[gd0 * HW_ + gw0]);
    float dsp1 = (tid < 128) ? __ldg(&dispb[gd1 * HW_ + gw1]) : 0.f;
    __syncthreads();

    #pragma unroll 1
    for (int mt = 0; mt < 12; ++mt) {
        const int w0 = mt * 16;

        float c0[3], c1[3], c2[3], c3[3];
        #pragma unroll
        for (int n = 0; n < 3; n++) { c0[n]=0.f; c1[n]=0.f; c2[n]=0.f; c3[n]=0.f; }
        #pragma unroll
        for (int ks = 0; ks < 8; ++ks) {
            const int kc = ks * 8;
            unsigned a0 = __float_as_uint(q_s[g * 68 + kc + tig]);
            unsigned a1 = __float_as_uint(q_s[(g + 8) * 68 + kc + tig]);
            unsigned a2 = __float_as_uint(q_s[g * 68 + kc + tig + 4]);
            unsigned a3 = __float_as_uint(q_s[(g + 8) * 68 + kc + tig + 4]);
            #pragma unroll
            for (int n = 0; n < 3; ++n) {
                const int x0 = warp * 24 + n * 8;
                unsigned b0 = __float_as_uint(kb_s[(kc + tig) * 200 + x0 + g]);
                unsigned b1 = __float_as_uint(kb_s[(kc + tig + 4) * 200 + x0 + g]);
                mma_tf32(c0[n], c1[n], c2[n], c3[n], a0, a1, a2, a3, b0, b1);
            }
        }
        __syncthreads();   // q_s(t) read done; gather(t-1) done

        #pragma unroll
        for (int n = 0; n < 3; ++n) {
            const int x0 = warp * 24 + n * 8;
            const int col = x0 + tig * 2;
            *(float2*)&S_s[g * 200 + col]       = make_float2(c0[n], c1[n]);
            *(float2*)&S_s[(g + 8) * 200 + col] = make_float2(c2[n], c3[n]);
        }
        if (mt < 11)
            *(float4*)&q_s[sm_ * 68 + sc4 * 4] = qv;
        if (mt < 10)
            qv = *(const float4*)(qbase + ((mt + 2) * 16 + sm_) * 64 + sc4 * 4);
        float nd0 = 0.f, nd1 = 0.f;
        if (mt < 11) {
            nd0 = __ldg(&dispb[gd0 * HW_ + w0 + 16 + gw0]);
            if (tid < 128) nd1 = __ldg(&dispb[gd1 * HW_ + w0 + 16 + gw1]);
        }
        __syncthreads();   // S_s + q_s(t+1) ready

        {
            float xs  = dsp0 * (192.0f / 191.0f) - 0.5f;
            float x0f = floorf(xs);
            float txf = xs - x0f;
            int ix0 = (int)x0f;
            float wx0 = (ix0 >= 0 && ix0 < W_) ? (1.0f - txf) : 0.0f;
            float wx1 = (ix0 + 1 >= 0 && ix0 + 1 < W_) ? txf : 0.0f;
            int x0c = min(max(ix0, 0), W_ - 1);
            int x1c = min(max(ix0 + 1, 0), W_ - 1);
            float rw = wsum * __ldg(&dubase[w0 + gw0]) + rho0;
            float sv = wx0 * (S_s[gw0 * 200 + x0c] + dvyb_s[x0c])
                     + wx1 * (S_s[gw0 * 200 + x1c] + dvyb_s[x1c])
                     + (wx0 + wx1) * rw;
            outb[gd0 * HW_ + w0 + gw0] = sv * 0.015625f;
        }
        if (tid < 128) {
            float xs  = dsp1 * (192.0f / 191.0f) - 0.5f;
            float x0f = floorf(xs);
            float txf = xs - x0f;
            int ix0 = (int)x0f;
            float wx0 = (ix0 >= 0 && ix0 < W_) ? (1.0f - txf) : 0.0f;
            float wx1 = (ix0 + 1 >= 0 && ix0 + 1 < W_) ? txf : 0.0f;
            int x0c = min(max(ix0, 0), W_ - 1);
            int x1c = min(max(ix0 + 1, 0), W_ - 1);
            float rw = wsum * __ldg(&dubase[w0 + gw1]) + rho0;
            float sv = wx0 * (S_s[gw1 * 200 + x0c] + dvyb_s[x0c])
                     + wx1 * (S_s[gw1 * 200 + x1c] + dvyb_s[x1c])
                     + (wx0 + wx1) * rw;
            outb[gd1 * HW_ + w0 + gw1] = sv * 0.015625f;
        }
        dsp0 = nd0; dsp1 = nd1;
    }
}

extern "C" void kernel_launch(void* const* d_in, const int* in_sizes, int n_in,
                              void* d_out, int out_size) {
    const float* x  = (const float*)d_in[0];
    const float* y  = (const float*)d_in[1];
    const float* d1 = (const float*)d_in[2];
    const float* d2 = (const float*)d_in[3];
    int wbase = (in_sizes[4] == 1) ? 5 : 4;
    const float* qw = (const float*)d_in[wbase + 0];
    const float* qb = (const float*)d_in[wbase + 1];
    const float* kw = (const float*)d_in[wbase + 2];
    const float* kb = (const float*)d_in[wbase + 3];
    float* out = (float*)d_out;

    cudaFuncSetAttribute(z_kernel,
                         cudaFuncAttributeMaxDynamicSharedMemorySize, 51200);
    cudaFuncSetAttribute(cost_kernel,
                         cudaFuncAttributeMaxDynamicSharedMemorySize, 69120);

    prep_kernel<<<65, 256>>>(qw, qb, kw, kb);
    z_kernel<<<dim3(H_, B_, 2), 256, 51200>>>(x, y);
    cost_kernel<<<dim3(H_, B_, 2), 256, 69120>>>(x, y, d1, d2, out);
}

// round 15
// speedup vs baseline: 1.0351x; 1.0351x over previous
#include <cuda_runtime.h>

#define B_ 4
#define C_ 64
#define H_ 64
#define W_ 192
#define D_ 24
#define HW_ (H_*W_)

__device__ float g_Mt[C_][C_];   // g_Mt[j][i] = sum_c kw[c][j]*qw[c][i]
__device__ float g_uv[2][C_];    // [0]=u (du weights), [1]=v (dv weights)
__device__ float g_s0;

__device__ __forceinline__ unsigned to_tf32(float f) {
    unsigned u;
    asm("cvt.rna.tf32.f32 %0, %1;" : "=r"(u) : "f"(f));
    return u;
}
__device__ __forceinline__ void mma_tf32(float& c0, float& c1, float& c2, float& c3,
                                         unsigned a0, unsigned a1, unsigned a2, unsigned a3,
                                         unsigned b0, unsigned b1) {
    asm volatile(
        "mma.sync.aligned.m16n8k8.row.col.f32.tf32.tf32.f32 "
        "{%0,%1,%2,%3}, {%4,%5,%6,%7}, {%8,%9}, {%0,%1,%2,%3};"
        : "+f"(c0), "+f"(c1), "+f"(c2), "+f"(c3)
        : "r"(a0), "r"(a1), "r"(a2), "r"(a3), "r"(b0), "r"(b1));
}

// ---------------------------------------------------------------------------
// Prep (verified): blocks 0..63 -> one M row each; block 64 -> u, v, s0.
// ---------------------------------------------------------------------------
__global__ void prep_kernel(const float* __restrict__ qw, const float* __restrict__ qb,
                            const float* __restrict__ kw, const float* __restrict__ kb)
{
    const int tid = threadIdx.x, bid = blockIdx.x;
    if (bid < 64) {
        const int j = bid, i = tid >> 2, q = tid & 3;
        float acc = 0.f;
        #pragma unroll
        for (int c = 0; c < 16; ++c)
            acc += __ldg(&kw[(q * 16 + c) * 64 + j]) * __ldg(&qw[(q * 16 + c) * 64 + i]);
        acc += __shfl_xor_sync(0xffffffffu, acc, 1);
        acc += __shfl_xor_sync(0xffffffffu, acc, 2);
        if (q == 0) g_Mt[j][i] = acc;
    } else {
        if (tid < 256) {
            const int m = tid >> 7, i = (tid >> 1) & 63, q = tid & 1;
            const float* wm = m ? kw : qw;
            const float* bm = m ? qb : kb;
            float acc = 0.f;
            #pragma unroll
            for (int c = 0; c < 32; ++c)
                acc += __ldg(&wm[(q * 32 + c) * 64 + i]) * __ldg(&bm[q * 32 + c]);
            acc += __shfl_xor_sync(0xffffffffu, acc, 1);
            if (q == 0) g_uv[m][i] = acc;
        }
        if (tid >= 224) {
            const int lane = tid & 31;
            float s = __ldg(&qb[lane]) * __ldg(&kb[lane])
                    + __ldg(&qb[lane + 32]) * __ldg(&kb[lane + 32]);
            s += __shfl_xor_sync(0xffffffffu, s, 1);
            s += __shfl_xor_sync(0xffffffffu, s, 2);
            s += __shfl_xor_sync(0xffffffffu, s, 4);
            s += __shfl_xor_sync(0xffffffffu, s, 8);
            s += __shfl_xor_sync(0xffffffffu, s, 16);
            if (lane == 0) g_s0 = s;
        }
    }
}

// ---------------------------------------------------------------------------
// Fused cost volume: per m-tile compute Z_tile = in_tile·M (8 mma) into q_s,
// then S = Z·Yb^T (24 mma), then gather. No g_Z round-trip, no z kernel.
// Block=(h,b,vol), 256 thr, 75392 B smem, 3 CTAs/SM.
// ---------------------------------------------------------------------------
__global__ __launch_bounds__(256, 3) void cost_kernel(
    const float* __restrict__ x, const float* __restrict__ y,
    const float* __restrict__ d1, const float* __restrict__ d2,
    float* __restrict__ out)
{
    extern __shared__ float sm[];
    float* kb_s   = sm;            // 64*200 = 12800 floats
    float* S_s    = sm + 12800;    // 16*200 = 3200
    float* q_s    = sm + 16000;    // 16*68  = 1088
    float* in2    = sm + 17088;    // 64*24  = 1536
    float* dvyb_s = sm + 18624;    // 192
    float* du_s   = sm + 18816;    // 2*16
    const int h = blockIdx.x, b = blockIdx.y, vol = blockIdx.z;
    const int tid = threadIdx.x;

    float ys  = h * (64.0f / 63.0f) - 0.5f;
    float y0f = floorf(ys);
    float ty  = ys - y0f;
    int iy0 = (int)y0f, iy1 = iy0 + 1;
    float wy0 = (iy0 >= 0 && iy0 < H_) ? (1.0f - ty) : 0.0f;
    float wy1 = (iy1 >= 0 && iy1 < H_) ? ty : 0.0f;
    int y0c = min(max(iy0, 0), H_ - 1);
    int y1c = min(max(iy1, 0), H_ - 1);
    const float wsum = wy0 + wy1;

    const float* srcB = (vol == 0) ? y : x;   // K-side raw source
    const float* srcA = (vol == 0) ? x : y;   // Q-side raw source

    // stage blended K rows -> kb_s[c][x] tf32
    #pragma unroll
    for (int e4 = tid; e4 < 3072; e4 += 256) {
        int c = e4 / 48, w4 = e4 - c * 48;
        const float* r0 = srcB + ((size_t)(b * 64 + c) * H_ + y0c) * W_ + w4 * 4;
        const float* r1 = srcB + ((size_t)(b * 64 + c) * H_ + y1c) * W_ + w4 * 4;
        float4 a = *(const float4*)r0, cc = *(const float4*)r1;
        *(uint4*)&kb_s[c * 200 + w4 * 4] =
            make_uint4(to_tf32(wy0 * a.x + wy1 * cc.x),
                       to_tf32(wy0 * a.y + wy1 * cc.y),
                       to_tf32(wy0 * a.z + wy1 * cc.z),
                       to_tf32(wy0 * a.w + wy1 * cc.w));
    }
    const float rho0 = wsum * g_s0;
    __syncthreads();   // kb_s ready (needed for dvyb)

    // dvyb[x] = sum_c kb_s[c][x] * v[c]   (kb already has y-validity folded)
    if (tid < 192) {
        float dv = 0.f;
        #pragma unroll 8
        for (int c = 0; c < 64; ++c)
            dv += kb_s[c * 200 + tid] * __ldg(&g_uv[1][c]);
        dvyb_s[tid] = dv;
    }

    const int warp = tid >> 5, lane = tid & 31;
    const int g = lane >> 2, tig = lane & 3;
    const int j0 = warp * 8;
    const int sc = tid >> 2, sq = tid & 3;      // in2 staging coords
    const int gd0 = tid >> 4, gw0 = tid & 15;   // gather mapping (R11 verified)
    const int gd1 = (tid + 256) >> 4, gw1 = tid & 15;
    const float* dispb = ((vol == 0) ? d1 : d2) + (size_t)b * D_ * HW_ + h * W_;
    const float* inbase = srcA + (size_t)(b * 64 + sc) * HW_ + h * W_;
    float* outb = out + ((size_t)(vol * B_ + b) * D_) * HW_ + h * W_;

    // prologue: stage input tile 0, prefetch tile 1 + disp tile 0
    {
        float4 v0 = *(const float4*)(inbase + sq * 4);
        *(float4*)&in2[sc * 24 + sq * 4] = v0;
    }
    float4 inreg = *(const float4*)(inbase + 16 + sq * 4);
    float dsp0 = __ldg(&dispb[gd0 * HW_ + gw0]);
    float dsp1 = (tid < 128) ? __ldg(&dispb[gd1 * HW_ + gw1]) : 0.f;
    __syncthreads();

    #pragma unroll 1
    for (int mt = 0; mt < 12; ++mt) {
        const int w0 = mt * 16;

        // --- A: Z-mma (in2 = tile mt), du_tile ---
        float z0 = 0.f, z1 = 0.f, z2 = 0.f, z3 = 0.f;
        #pragma unroll
        for (int ks = 0; ks < 8; ++ks) {
            unsigned a0 = to_tf32(in2[(ks * 8 + tig) * 24 + g]);
            unsigned a1 = to_tf32(in2[(ks * 8 + tig) * 24 + g + 8]);
            unsigned a2 = to_tf32(in2[(ks * 8 + tig + 4) * 24 + g]);
            unsigned a3 = to_tf32(in2[(ks * 8 + tig + 4) * 24 + g + 8]);
            unsigned b0 = to_tf32(__ldg(&g_Mt[j0 + g][ks * 8 + tig]));
            unsigned b1 = to_tf32(__ldg(&g_Mt[j0 + g][ks * 8 + tig + 4]));
            mma_tf32(z0, z1, z2, z3, a0, a1, a2, a3, b0, b1);
        }
        if (tid < 64) {   // du for this tile's 16 pixels
            int pix = tid >> 2, q = tid & 3;
            float du = 0.f;
            #pragma unroll
            for (int c = 0; c < 16; ++c)
                du += in2[(q * 16 + c) * 24 + pix] * __ldg(&g_uv[0][q * 16 + c]);
            du += __shfl_xor_sync(0xffffffffu, du, 1);
            du += __shfl_xor_sync(0xffffffffu, du, 2);
            if (q == 0) du_s[(mt & 1) * 16 + pix] = du;
        }
        __syncthreads();   // in2(mt)+q_s consumed; gather(mt-1) done

        // --- B: STS Z -> q_s; in2 <- tile mt+1; prefetch tile mt+2 ---
        *(uint2*)&q_s[g * 68 + j0 + 2 * tig] = make_uint2(to_tf32(z0), to_tf32(z1));
        *(uint2*)&q_s[(g + 8) * 68 + j0 + 2 * tig] = make_uint2(to_tf32(z2), to_tf32(z3));
        if (mt < 11)
            *(float4*)&in2[sc * 24 + sq * 4] = inreg;
        if (mt < 10)
            inreg = *(const float4*)(inbase + (mt + 2) * 16 + sq * 4);
        __syncthreads();   // q_s(mt) + in2(mt+1) ready

        // --- C: S-mma + STS S + disp prefetch ---
        float c0[3], c1[3], c2[3], c3[3];
        #pragma unroll
        for (int n = 0; n < 3; n++) { c0[n]=0.f; c1[n]=0.f; c2[n]=0.f; c3[n]=0.f; }
        #pragma unroll
        for (int ks = 0; ks < 8; ++ks) {
            const int kc = ks * 8;
            unsigned a0 = __float_as_uint(q_s[g * 68 + kc + tig]);
            unsigned a1 = __float_as_uint(q_s[(g + 8) * 68 + kc + tig]);
            unsigned a2 = __float_as_uint(q_s[g * 68 + kc + tig + 4]);
            unsigned a3 = __float_as_uint(q_s[(g + 8) * 68 + kc + tig + 4]);
            #pragma unroll
            for (int n = 0; n < 3; ++n) {
                const int x0 = warp * 24 + n * 8;
                unsigned b0 = __float_as_uint(kb_s[(kc + tig) * 200 + x0 + g]);
                unsigned b1 = __float_as_uint(kb_s[(kc + tig + 4) * 200 + x0 + g]);
                mma_tf32(c0[n], c1[n], c2[n], c3[n], a0, a1, a2, a3, b0, b1);
            }
        }
        #pragma unroll
        for (int n = 0; n < 3; ++n) {
            const int x0 = warp * 24 + n * 8;
            const int col = x0 + tig * 2;
            *(float2*)&S_s[g * 200 + col]       = make_float2(c0[n], c1[n]);
            *(float2*)&S_s[(g + 8) * 200 + col] = make_float2(c2[n], c3[n]);
        }
        float nd0 = 0.f, nd1 = 0.f;
        if (mt < 11) {
            nd0 = __ldg(&dispb[gd0 * HW_ + w0 + 16 + gw0]);
            if (tid < 128) nd1 = __ldg(&dispb[gd1 * HW_ + w0 + 16 + gw1]);
        }
        __syncthreads();   // S_s + du_s ready

        // --- D: gather (R11-verified mapping) ---
        {
            float xs  = dsp0 * (192.0f / 191.0f) - 0.5f;
            float x0f = floorf(xs);
            float txf = xs - x0f;
            int ix0 = (int)x0f;
            float wx0 = (ix0 >= 0 && ix0 < W_) ? (1.0f - txf) : 0.0f;
            float wx1 = (ix0 + 1 >= 0 && ix0 + 1 < W_) ? txf : 0.0f;
            int x0c = min(max(ix0, 0), W_ - 1);
            int x1c = min(max(ix0 + 1, 0), W_ - 1);
            float rw = wsum * du_s[(mt & 1) * 16 + gw0] + rho0;
            float sv = wx0 * (S_s[gw0 * 200 + x0c] + dvyb_s[x0c])
                     + wx1 * (S_s[gw0 * 200 + x1c] + dvyb_s[x1c])
                     + (wx0 + wx1) * rw;
            outb[gd0 * HW_ + w0 + gw0] = sv * 0.015625f;
        }
        if (tid < 128) {
            float xs  = dsp1 * (192.0f / 191.0f) - 0.5f;
            float x0f = floorf(xs);
            float txf = xs - x0f;
            int ix0 = (int)x0f;
            float wx0 = (ix0 >= 0 && ix0 < W_) ? (1.0f - txf) : 0.0f;
            float wx1 = (ix0 + 1 >= 0 && ix0 + 1 < W_) ? txf : 0.0f;
            int x0c = min(max(ix0, 0), W_ - 1);
            int x1c = min(max(ix0 + 1, 0), W_ - 1);
            float rw = wsum * du_s[(mt & 1) * 16 + gw1] + rho0;
            float sv = wx0 * (S_s[gw1 * 200 + x0c] + dvyb_s[x0c])
                     + wx1 * (S_s[gw1 * 200 + x1c] + dvyb_s[x1c])
                     + (wx0 + wx1) * rw;
            outb[gd1 * HW_ + w0 + gw1] = sv * 0.015625f;
        }
        dsp0 = nd0; dsp1 = nd1;
    }
}

extern "C" void kernel_launch(void* const* d_in, const int* in_sizes, int n_in,
                              void* d_out, int out_size) {
    const float* x  = (const float*)d_in[0];
    const float* y  = (const float*)d_in[1];
    const float* d1 = (const float*)d_in[2];
    const float* d2 = (const float*)d_in[3];
    int wbase = (in_sizes[4] == 1) ? 5 : 4;
    const float* qw = (const float*)d_in[wbase + 0];
    const float* qb = (const float*)d_in[wbase + 1];
    const float* kw = (const float*)d_in[wbase + 2];
    const float* kb = (const float*)d_in[wbase + 3];
    float* out = (float*)d_out;

    cudaFuncSetAttribute(cost_kernel,
                         cudaFuncAttributeMaxDynamicSharedMemorySize, 75392);

    prep_kernel<<<65, 256>>>(qw, qb, kw, kb);
    cost_kernel<<<dim3(H_, B_, 2), 256, 75392>>>(x, y, d1, d2, out);
}

// round 16
// speedup vs baseline: 1.0758x; 1.0393x over previous
#include <cuda_runtime.h>

#define B_ 4
#define C_ 64
#define H_ 64
#define W_ 192
#define D_ 24
#define HW_ (H_*W_)

__device__ float g_Mt[C_][C_];   // g_Mt[j][i] = sum_c kw[c][j]*qw[c][i]
__device__ float g_uv[2][C_];    // [0]=u (du weights), [1]=v (dv weights)
__device__ float g_s0;

__device__ __forceinline__ unsigned to_tf32(float f) {
    unsigned u;
    asm("cvt.rna.tf32.f32 %0, %1;" : "=r"(u) : "f"(f));
    return u;
}
__device__ __forceinline__ void mma_tf32(float& c0, float& c1, float& c2, float& c3,
                                         unsigned a0, unsigned a1, unsigned a2, unsigned a3,
                                         unsigned b0, unsigned b1) {
    asm volatile(
        "mma.sync.aligned.m16n8k8.row.col.f32.tf32.tf32.f32 "
        "{%0,%1,%2,%3}, {%4,%5,%6,%7}, {%8,%9}, {%0,%1,%2,%3};"
        : "+f"(c0), "+f"(c1), "+f"(c2), "+f"(c3)
        : "r"(a0), "r"(a1), "r"(a2), "r"(a3), "r"(b0), "r"(b1));
}

// ---------------------------------------------------------------------------
// Prep (verified): blocks 0..63 -> one M row each; block 64 -> u, v, s0.
// ---------------------------------------------------------------------------
__global__ void prep_kernel(const float* __restrict__ qw, const float* __restrict__ qb,
                            const float* __restrict__ kw, const float* __restrict__ kb)
{
    const int tid = threadIdx.x, bid = blockIdx.x;
    if (bid < 64) {
        const int j = bid, i = tid >> 2, q = tid & 3;
        float acc = 0.f;
        #pragma unroll
        for (int c = 0; c < 16; ++c)
            acc += __ldg(&kw[(q * 16 + c) * 64 + j]) * __ldg(&qw[(q * 16 + c) * 64 + i]);
        acc += __shfl_xor_sync(0xffffffffu, acc, 1);
        acc += __shfl_xor_sync(0xffffffffu, acc, 2);
        if (q == 0) g_Mt[j][i] = acc;
    } else {
        if (tid < 256) {
            const int m = tid >> 7, i = (tid >> 1) & 63, q = tid & 1;
            const float* wm = m ? kw : qw;
            const float* bm = m ? qb : kb;
            float acc = 0.f;
            #pragma unroll
            for (int c = 0; c < 32; ++c)
                acc += __ldg(&wm[(q * 32 + c) * 64 + i]) * __ldg(&bm[q * 32 + c]);
            acc += __shfl_xor_sync(0xffffffffu, acc, 1);
            if (q == 0) g_uv[m][i] = acc;
        }
        if (tid >= 224) {
            const int lane = tid & 31;
            float s = __ldg(&qb[lane]) * __ldg(&kb[lane])
                    + __ldg(&qb[lane + 32]) * __ldg(&kb[lane + 32]);
            s += __shfl_xor_sync(0xffffffffu, s, 1);
            s += __shfl_xor_sync(0xffffffffu, s, 2);
            s += __shfl_xor_sync(0xffffffffu, s, 4);
            s += __shfl_xor_sync(0xffffffffu, s, 8);
            s += __shfl_xor_sync(0xffffffffu, s, 16);
            if (lane == 0) g_s0 = s;
        }
    }
}

// ---------------------------------------------------------------------------
// Fused cost volume, T-form: prologue computes T = contraction(M, Kb) in
// place over kb_s (column-disjoint per warp). Main loop per 16-pixel tile:
// S = in·T (24 mma, A from raw in2), STS S, gather. No q_s, 2 syncs/tile.
// Block=(h,b,vol), 256 thr, 71040 B smem, 3 CTAs/SM.
// ---------------------------------------------------------------------------
__global__ __launch_bounds__(256, 3) void cost_kernel(
    const float* __restrict__ x, const float* __restrict__ y,
    const float* __restrict__ d1, const float* __restrict__ d2,
    float* __restrict__ out)
{
    extern __shared__ float sm[];
    float* kb_s   = sm;            // [64][200] = 12800 (becomes T in place)
    float* S_s    = sm + 12800;    // [16][200] = 3200
    float* in2    = sm + 16000;    // [64][24]  = 1536
    float* dvyb_s = sm + 17536;    // 192
    float* du_s   = sm + 17728;    // 32          -> total 17760 fl = 71040 B
    float* Mt_s   = sm + 12800;    // overlay [64][72]=4608 <= 4736 (S_s+in2)
    const int h = blockIdx.x, b = blockIdx.y, vol = blockIdx.z;
    const int tid = threadIdx.x;

    float ys  = h * (64.0f / 63.0f) - 0.5f;
    float y0f = floorf(ys);
    float ty  = ys - y0f;
    int iy0 = (int)y0f, iy1 = iy0 + 1;
    float wy0 = (iy0 >= 0 && iy0 < H_) ? (1.0f - ty) : 0.0f;
    float wy1 = (iy1 >= 0 && iy1 < H_) ? ty : 0.0f;
    int y0c = min(max(iy0, 0), H_ - 1);
    int y1c = min(max(iy1, 0), H_ - 1);
    const float wsum = wy0 + wy1;

    const float* srcB = (vol == 0) ? y : x;   // K-side raw source
    const float* srcA = (vol == 0) ? x : y;   // Q-side raw source

    // ---- phase 1: stage blended K rows (tf32) + Mt (tf32, stride 72) ----
    #pragma unroll
    for (int e4 = tid; e4 < 3072; e4 += 256) {
        int c = e4 / 48, w4 = e4 - c * 48;
        const float* r0 = srcB + ((size_t)(b * 64 + c) * H_ + y0c) * W_ + w4 * 4;
        const float* r1 = srcB + ((size_t)(b * 64 + c) * H_ + y1c) * W_ + w4 * 4;
        float4 a = *(const float4*)r0, cc = *(const float4*)r1;
        *(uint4*)&kb_s[c * 200 + w4 * 4] =
            make_uint4(to_tf32(wy0 * a.x + wy1 * cc.x),
                       to_tf32(wy0 * a.y + wy1 * cc.y),
                       to_tf32(wy0 * a.z + wy1 * cc.z),
                       to_tf32(wy0 * a.w + wy1 * cc.w));
    }
    #pragma unroll
    for (int e4 = tid; e4 < 1024; e4 += 256) {
        int j = e4 >> 4, i4 = e4 & 15;
        float4 v = *(const float4*)&g_Mt[j][i4 * 4];
        *(uint4*)&Mt_s[j * 72 + i4 * 4] =
            make_uint4(to_tf32(v.x), to_tf32(v.y), to_tf32(v.z), to_tf32(v.w));
    }
    const float rho0 = wsum * g_s0;
    __syncthreads();

    const int warp = tid >> 5, lane = tid & 31;
    const int g = lane >> 2, tig = lane & 3;

    // ---- phase 2: dvyb (reads all kb cols) + T-mma group 0 (reads only) ----
    float dvv = 0.f;
    if (tid < 192) {
        #pragma unroll 8
        for (int c = 0; c < 64; ++c)
            dvv += kb_s[c * 200 + tid] * __ldg(&g_uv[1][c]);
    }
    float t0[4], t1[4], t2[4], t3[4];
    {
        const int xn = warp * 24;
        #pragma unroll
        for (int mi = 0; mi < 4; mi++) { t0[mi]=0.f; t1[mi]=0.f; t2[mi]=0.f; t3[mi]=0.f; }
        #pragma unroll
        for (int ks = 0; ks < 8; ++ks) {
            const int kc = ks * 8;
            unsigned b0 = __float_as_uint(kb_s[(kc + tig) * 200 + xn + g]);
            unsigned b1 = __float_as_uint(kb_s[(kc + tig + 4) * 200 + xn + g]);
            #pragma unroll
            for (int mi = 0; mi < 4; ++mi) {
                unsigned a0 = __float_as_uint(Mt_s[(kc + tig) * 72 + mi * 16 + g]);
                unsigned a1 = __float_as_uint(Mt_s[(kc + tig) * 72 + mi * 16 + g + 8]);
                unsigned a2 = __float_as_uint(Mt_s[(kc + tig + 4) * 72 + mi * 16 + g]);
                unsigned a3 = __float_as_uint(Mt_s[(kc + tig + 4) * 72 + mi * 16 + g + 8]);
                mma_tf32(t0[mi], t1[mi], t2[mi], t3[mi], a0, a1, a2, a3, b0, b1);
            }
        }
    }
    if (tid < 192) dvyb_s[tid] = dvv;
    __syncthreads();   // all kb reads (dvyb + group0) done before any T write

    // ---- phase 3: STS T0; compute+STS T1, T2 (column-disjoint per warp) ----
    #pragma unroll
    for (int nn = 0; nn < 3; ++nn) {
        const int xn = warp * 24 + nn * 8;
        if (nn > 0) {
            #pragma unroll
            for (int mi = 0; mi < 4; mi++) { t0[mi]=0.f; t1[mi]=0.f; t2[mi]=0.f; t3[mi]=0.f; }
            #pragma unroll
            for (int ks = 0; ks < 8; ++ks) {
                const int kc = ks * 8;
                unsigned b0 = __float_as_uint(kb_s[(kc + tig) * 200 + xn + g]);
                unsigned b1 = __float_as_uint(kb_s[(kc + tig + 4) * 200 + xn + g]);
                #pragma unroll
                for (int mi = 0; mi < 4; ++mi) {
                    unsigned a0 = __float_as_uint(Mt_s[(kc + tig) * 72 + mi * 16 + g]);
                    unsigned a1 = __float_as_uint(Mt_s[(kc + tig) * 72 + mi * 16 + g + 8]);
                    unsigned a2 = __float_as_uint(Mt_s[(kc + tig + 4) * 72 + mi * 16 + g]);
                    unsigned a3 = __float_as_uint(Mt_s[(kc + tig + 4) * 72 + mi * 16 + g + 8]);
                    mma_tf32(t0[mi], t1[mi], t2[mi], t3[mi], a0, a1, a2, a3, b0, b1);
                }
            }
        }
        #pragma unroll
        for (int mi = 0; mi < 4; ++mi) {
            *(uint2*)&kb_s[(mi * 16 + g) * 200 + xn + 2 * tig] =
                make_uint2(to_tf32(t0[mi]), to_tf32(t1[mi]));
            *(uint2*)&kb_s[(mi * 16 + g + 8) * 200 + xn + 2 * tig] =
                make_uint2(to_tf32(t2[mi]), to_tf32(t3[mi]));
        }
    }
    __syncthreads();   // T complete; Mt_s dead -> S_s / in2 usable

    // ---- main loop ----
    const int sc = tid >> 2, sq = tid & 3;      // in2 staging coords
    const int gd0 = tid >> 4, gw0 = tid & 15;   // gather mapping (verified)
    const int gd1 = (tid + 256) >> 4, gw1 = tid & 15;
    const float* dispb = ((vol == 0) ? d1 : d2) + (size_t)b * D_ * HW_ + h * W_;
    const float* inbase = srcA + (size_t)(b * 64 + sc) * HW_ + h * W_;
    float* outb = out + ((size_t)(vol * B_ + b) * D_) * HW_ + h * W_;

    *(float4*)&in2[sc * 24 + sq * 4] = *(const float4*)(inbase + sq * 4);
    float4 inreg = *(const float4*)(inbase + 16 + sq * 4);
    float dsp0 = __ldg(&dispb[gd0 * HW_ + gw0]);
    float dsp1 = (tid < 128) ? __ldg(&dispb[gd1 * HW_ + gw1]) : 0.f;
    __syncthreads();

    #pragma unroll 1
    for (int mt = 0; mt < 12; ++mt) {
        const int w0 = mt * 16;

        // --- a: S-mma (A = raw in2 tile, B = T) + du ---
        float c0[3], c1[3], c2[3], c3[3];
        #pragma unroll
        for (int n = 0; n < 3; n++) { c0[n]=0.f; c1[n]=0.f; c2[n]=0.f; c3[n]=0.f; }
        #pragma unroll
        for (int ks = 0; ks < 8; ++ks) {
            const int kc = ks * 8;
            unsigned a0 = to_tf32(in2[(kc + tig) * 24 + g]);
            unsigned a1 = to_tf32(in2[(kc + tig) * 24 + g + 8]);
            unsigned a2 = to_tf32(in2[(kc + tig + 4) * 24 + g]);
            unsigned a3 = to_tf32(in2[(kc + tig + 4) * 24 + g + 8]);
            #pragma unroll
            for (int n = 0; n < 3; ++n) {
                const int x0 = warp * 24 + n * 8;
                unsigned b0 = __float_as_uint(kb_s[(kc + tig) * 200 + x0 + g]);
                unsigned b1 = __float_as_uint(kb_s[(kc + tig + 4) * 200 + x0 + g]);
                mma_tf32(c0[n], c1[n], c2[n], c3[n], a0, a1, a2, a3, b0, b1);
            }
        }
        if (tid < 64) {   // du for this tile's 16 pixels
            int pix = tid >> 2, q = tid & 3;
            float du = 0.f;
            #pragma unroll
            for (int c = 0; c < 16; ++c)
                du += in2[(q * 16 + c) * 24 + pix] * __ldg(&g_uv[0][q * 16 + c]);
            du += __shfl_xor_sync(0xffffffffu, du, 1);
            du += __shfl_xor_sync(0xffffffffu, du, 2);
            if (q == 0) du_s[(mt & 1) * 16 + pix] = du;
        }
        __syncthreads();   // in2(mt) consumed; gather(mt-1) done

        // --- b: STS S; in2 <- tile mt+1; prefetch tile mt+2 ---
        #pragma unroll
        for (int n = 0; n < 3; ++n) {
            const int x0 = warp * 24 + n * 8;
            const int col = x0 + tig * 2;
            *(float2*)&S_s[g * 200 + col]       = make_float2(c0[n], c1[n]);
            *(float2*)&S_s[(g + 8) * 200 + col] = make_float2(c2[n], c3[n]);
        }
        if (mt < 11)
            *(float4*)&in2[sc * 24 + sq * 4] = inreg;
        if (mt < 10)
            inreg = *(const float4*)(inbase + (mt + 2) * 16 + sq * 4);
        __syncthreads();   // S_s + du_s + in2(mt+1) ready

        // --- c: gather + disp prefetch ---
        float nd0 = 0.f, nd1 = 0.f;
        if (mt < 11) {
            nd0 = __ldg(&dispb[gd0 * HW_ + w0 + 16 + gw0]);
            if (tid < 128) nd1 = __ldg(&dispb[gd1 * HW_ + w0 + 16 + gw1]);
        }
        {
            float xs  = dsp0 * (192.0f / 191.0f) - 0.5f;
            float x0f = floorf(xs);
            float txf = xs - x0f;
            int ix0 = (int)x0f;
            float wx0 = (ix0 >= 0 && ix0 < W_) ? (1.0f - txf) : 0.0f;
            float wx1 = (ix0 + 1 >= 0 && ix0 + 1 < W_) ? txf : 0.0f;
            int x0c = min(max(ix0, 0), W_ - 1);
            int x1c = min(max(ix0 + 1, 0), W_ - 1);
            float rw = wsum * du_s[(mt & 1) * 16 + gw0] + rho0;
            float sv = wx0 * (S_s[gw0 * 200 + x0c] + dvyb_s[x0c])
                     + wx1 * (S_s[gw0 * 200 + x1c] + dvyb_s[x1c])
                     + (wx0 + wx1) * rw;
            outb[gd0 * HW_ + w0 + gw0] = sv * 0.015625f;
        }
        if (tid < 128) {
            float xs  = dsp1 * (192.0f / 191.0f) - 0.5f;
            float x0f = floorf(xs);
            float txf = xs - x0f;
            int ix0 = (int)x0f;
            float wx0 = (ix0 >= 0 && ix0 < W_) ? (1.0f - txf) : 0.0f;
            float wx1 = (ix0 + 1 >= 0 && ix0 + 1 < W_) ? txf : 0.0f;
            int x0c = min(max(ix0, 0), W_ - 1);
            int x1c = min(max(ix0 + 1, 0), W_ - 1);
            float rw = wsum * du_s[(mt & 1) * 16 + gw1] + rho0;
            float sv = wx0 * (S_s[gw1 * 200 + x0c] + dvyb_s[x0c])
                     + wx1 * (S_s[gw1 * 200 + x1c] + dvyb_s[x1c])
                     + (wx0 + wx1) * rw;
            outb[gd1 * HW_ + w0 + gw1] = sv * 0.015625f;
        }
        dsp0 = nd0; dsp1 = nd1;
    }
}

extern "C" void kernel_launch(void* const* d_in, const int* in_sizes, int n_in,
                              void* d_out, int out_size) {
    const float* x  = (const float*)d_in[0];
    const float* y  = (const float*)d_in[1];
    const float* d1 = (const float*)d_in[2];
    const float* d2 = (const float*)d_in[3];
    int wbase = (in_sizes[4] == 1) ? 5 : 4;
    const float* qw = (const float*)d_in[wbase + 0];
    const float* qb = (const float*)d_in[wbase + 1];
    const float* kw = (const float*)d_in[wbase + 2];
    const float* kb = (const float*)d_in[wbase + 3];
    float* out = (float*)d_out;

    cudaFuncSetAttribute(cost_kernel,
                         cudaFuncAttributeMaxDynamicSharedMemorySize, 71040);

    prep_kernel<<<65, 256>>>(qw, qb, kw, kb);
    cost_kernel<<<dim3(H_, B_, 2), 256, 71040>>>(x, y, d1, d2, out);
}